// round 16
// baseline (speedup 1.0000x reference)
#include <cuda_runtime.h>
#include <cuda_bf16.h>
#include <math.h>
#include <stdint.h>

#define NAC 20000
#define NBC 20000
#define NNC 40000
#define EC  150000
#define MAXCAND 2048

// ---------------------------------------------------------------------------
// Scratch (static device globals)
// ---------------------------------------------------------------------------
__device__ float g_h[NNC * 128];             // node features [a;b]
__device__ float g_feat_a[NAC * 640];        // q|kt0|vt0|kt1|vt1 for type a
__device__ float g_feat_b[NBC * 384];        // q|kt2|vt2 for type b
__device__ float g_bcat[3 * 1024];           // folded biases
__device__ __align__(16) __nv_bfloat16 g_wA[24 * 32768];  // split/swizzled wcat tiles
__device__ __align__(16) __nv_bfloat16 g_wO[6 * 32768];   // split/swizzled Wout tiles
__device__ float g_agg[NNC * 128];
__device__ int   g_deg[NNC + 1];
__device__ int   g_rowptr[NNC + 1];
__device__ int   g_cursor[NNC];
__device__ int   g_bsum[64];
__device__ int   g_cse[3 * EC];              // src | et<<29
__device__ float g_x1[NNC];
__device__ float g_score[NNC];
__device__ float g_cval[MAXCAND];
__device__ int   g_cidx[MAXCAND];

__device__ __forceinline__ float gelu_f(float x) {
    return 0.5f * x * (1.0f + erff(x * 0.7071067811865475f));
}
__device__ __forceinline__ uint32_t smem_u32(const void* p) {
    uint32_t a;
    asm("{ .reg .u64 t; cvta.to.shared.u64 t, %1; cvt.u32.u64 %0, t; }" : "=r"(a) : "l"(p));
    return a;
}
__device__ __forceinline__ void mma_bf16(float* c, const uint32_t* a, const uint32_t* b) {
    asm volatile(
        "mma.sync.aligned.m16n8k16.row.col.f32.bf16.bf16.f32 "
        "{%0,%1,%2,%3}, {%4,%5,%6,%7}, {%8,%9}, {%0,%1,%2,%3};"
        : "+f"(c[0]), "+f"(c[1]), "+f"(c[2]), "+f"(c[3])
        : "r"(a[0]), "r"(a[1]), "r"(a[2]), "r"(a[3]), "r"(b[0]), "r"(b[1]));
}
__device__ __forceinline__ void ldsm_x4(uint32_t* r, uint32_t addr) {
    asm volatile("ldmatrix.sync.aligned.m8n8.x4.shared.b16 {%0,%1,%2,%3}, [%4];"
                 : "=r"(r[0]), "=r"(r[1]), "=r"(r[2]), "=r"(r[3]) : "r"(addr));
}
#define CP_ASYNC16(dst, src) \
    asm volatile("cp.async.cg.shared.global [%0], [%1], 16;" :: "r"(dst), "l"(src))
#define CP_COMMIT() asm volatile("cp.async.commit_group;" ::: "memory")
#define CP_WAIT0()  asm volatile("cp.async.wait_group 0;" ::: "memory")

// split 8 consecutive floats into packed bf16 hi (16B) and lo (16B)
__device__ __forceinline__ void split8(const float* f, uint4& hi, uint4& lo) {
    uint32_t h[4], l[4];
#pragma unroll
    for (int j = 0; j < 4; j++) {
        float f0 = f[2 * j], f1 = f[2 * j + 1];
        __nv_bfloat16 b0 = __float2bfloat16_rn(f0);
        __nv_bfloat16 b1 = __float2bfloat16_rn(f1);
        float r0 = f0 - __bfloat162float(b0);
        float r1 = f1 - __bfloat162float(b1);
        __nv_bfloat162 hh = __halves2bfloat162(b0, b1);
        __nv_bfloat162 ll = __halves2bfloat162(__float2bfloat16_rn(r0),
                                               __float2bfloat16_rn(r1));
        h[j] = *(uint32_t*)&hh;
        l[j] = *(uint32_t*)&ll;
    }
    hi = make_uint4(h[0], h[1], h[2], h[3]);
    lo = make_uint4(l[0], l[1], l[2], l[3]);
}

// ---------------------------------------------------------------------------
// Folded weight value (q | per-edge-type kt/vt). i==128 -> bias.
// ---------------------------------------------------------------------------
__device__ float fold_val(const float* __restrict__ Wkqv, const float* __restrict__ bkqv,
                          const float* __restrict__ arel, const float* __restrict__ mrel,
                          int L, int i, int c) {
    int type = (c >= 640) ? 1 : 0;
    int cc = c - (type ? 640 : 0);
    int part = cc >> 7, wi = cc & 127;
    const float* Wrow = (i < 128) ? Wkqv + ((size_t)(L * 2 + type) * 128 + i) * 384
                                  : bkqv + (size_t)(L * 2 + type) * 384;
    if (part == 0) return Wrow[128 + wi];
    int et, kv;
    if (type == 0) { et = (part - 1) >> 1; kv = (part - 1) & 1; }
    else           { et = 2;               kv = part - 1; }
    int h = wi >> 5, e2 = wi & 31;
    const float* rel = (kv ? mrel : arel) + ((size_t)(L * 3 + et) * 4 + h) * 1024 + e2;
    const float* ws = Wrow + (kv ? 256 : 0) + h * 32;
    float s = 0.f;
#pragma unroll
    for (int d = 0; d < 32; d++) s += ws[d] * rel[d * 32];
    return s;
}

__global__ void k_fold2(const float* __restrict__ Wkqv, const float* __restrict__ bkqv,
                        const float* __restrict__ Wout,
                        const float* __restrict__ arel, const float* __restrict__ mrel,
                        __nv_bfloat16* __restrict__ wA, __nv_bfloat16* __restrict__ wO,
                        float* __restrict__ bcat) {
    int idx = blockIdx.x * blockDim.x + threadIdx.x;
    const int PER = 16384;
    const int WTOT = 30 * PER;
    if (idx < WTOT) {
        int t = idx / PER, e = idx % PER;
        int k = e >> 7, n = e & 127;
        float v;
        __nv_bfloat16* dst;
        if (t < 24) {
            int L = t >> 3, xt = t & 7;
            int c = (xt < 5) ? xt * 128 + n : 640 + (xt - 5) * 128 + n;
            v = fold_val(Wkqv, bkqv, arel, mrel, L, k, c);
            dst = wA + (size_t)t * 32768;
        } else {
            v = Wout[(size_t)(t - 24) * 16384 + k * 128 + n];
            dst = wO + (size_t)(t - 24) * 32768;
        }
        __nv_bfloat16 hi = __float2bfloat16_rn(v);
        __nv_bfloat16 lo = __float2bfloat16_rn(v - __bfloat162float(hi));
        int chunk = k >> 6, kk = k & 63;
        int ksw = ((kk * 2) ^ ((n & 7) << 4)) >> 1;
        dst += chunk * 16384;
        dst[n * 64 + ksw] = hi;
        dst[8192 + n * 64 + ksw] = lo;
    } else if (idx < WTOT + 3 * 1024) {
        int j = idx - WTOT;
        int L = j >> 10, c = j & 1023;
        bcat[L * 1024 + c] = fold_val(Wkqv, bkqv, arel, mrel, L, 128, c);
    }
}

// ---------------------------------------------------------------------------
// GEMM core: 128x128 tile, acc = bf16-2split(A) @ Wtile. 8 warps (2M x 4N).
// (Frozen: single-buffered, 64KB smem, regs=128, 2 CTA/SM.)
// ---------------------------------------------------------------------------
#define SMEM_GEMM 65536
template <bool GELU_A>
__device__ __forceinline__ void gemm_tile(char* smem, uint32_t sb,
                                          const float* __restrict__ A, int lda, int arows,
                                          const __nv_bfloat16* __restrict__ blob,
                                          float acc[4][4][4]) {
    const int AHI = 0, ALO = 16384, BHI = 32768;
    int tid = threadIdx.x, lane = tid & 31, wid = tid >> 5;
    int warp_m = wid & 1, warp_n = wid >> 1;
    int lm = lane & 15;
    int lk = (lane >> 4) << 4;

    for (int chunk = 0; chunk < 2; chunk++) {
        {
            const char* src = (const char*)(blob + chunk * 16384);
            uint32_t dst = sb + BHI;
#pragma unroll
            for (int it = 0; it < 8; it++) {
                int i = it * 256 + tid;
                CP_ASYNC16(dst + i * 16, src + i * 16);
            }
            CP_COMMIT();
        }
#pragma unroll
        for (int it = 0; it < 4; it++) {
            int i = it * 256 + tid;
            int m = i >> 3, kg = i & 7;
            float f[8] = {};
            if (m < arows) {
                const float* ap = A + (size_t)m * lda + chunk * 64 + kg * 8;
                *(float4*)&f[0] = *(const float4*)ap;
                *(float4*)&f[4] = *(const float4*)(ap + 4);
            }
            if (GELU_A) {
#pragma unroll
                for (int j = 0; j < 8; j++) f[j] = gelu_f(f[j]);
            }
            uint4 hi, lo;
            split8(f, hi, lo);
            int off = m * 128 + ((kg * 16) ^ ((m & 7) << 4));
            *(uint4*)(smem + AHI + off) = hi;
            *(uint4*)(smem + ALO + off) = lo;
        }
        CP_WAIT0();
        __syncthreads();

#pragma unroll
        for (int k16 = 0; k16 < 4; k16++) {
            int kb = k16 * 32 + lk;
            uint32_t bh[2][4], bl[2][4];
#pragma unroll
            for (int ntp = 0; ntp < 2; ntp++) {
                int n = warp_n * 32 + ntp * 16 + lm;
                int off = n * 128 + (kb ^ ((n & 7) << 4));
                ldsm_x4(bh[ntp], sb + BHI + off);
                ldsm_x4(bl[ntp], sb + BHI + 16384 + off);
            }
#pragma unroll
            for (int mt = 0; mt < 4; mt++) {
                int m = warp_m * 64 + mt * 16 + lm;
                int off = m * 128 + (kb ^ ((m & 7) << 4));
                uint32_t ah[4], al[4];
                ldsm_x4(ah, sb + AHI + off);
                ldsm_x4(al, sb + ALO + off);
#pragma unroll
                for (int nt = 0; nt < 4; nt++) {
                    uint32_t bfh[2] = {bh[nt >> 1][nt & 1], bh[nt >> 1][(nt & 1) + 2]};
                    uint32_t bfl[2] = {bl[nt >> 1][nt & 1], bl[nt >> 1][(nt & 1) + 2]};
                    mma_bf16(acc[mt][nt], ah, bfh);
                    mma_bf16(acc[mt][nt], ah, bfl);
                    mma_bf16(acc[mt][nt], al, bfh);
                }
            }
        }
        __syncthreads();
    }
}

// ---------------------------------------------------------------------------
// Merged feature GEMM (both node types in one launch).
// ---------------------------------------------------------------------------
__global__ void __launch_bounds__(256)
k_gemm_feat(const float* __restrict__ Aa, const float* __restrict__ Ab,
            int Ma, int Mb,
            const __nv_bfloat16* __restrict__ wblob, const float* __restrict__ bias,
            float* __restrict__ Ca, float* __restrict__ Cb) {
    extern __shared__ __align__(128) char smem[];
    uint32_t sb = smem_u32(smem);
    int xt = blockIdx.x;
    bool tb = xt >= 5;
    const float* A = tb ? Ab : Aa;
    int M = tb ? Mb : Ma;
    float* C = tb ? Cb : Ca;
    int ldc = tb ? 384 : 640;
    int coloff = tb ? (xt - 5) * 128 : xt * 128;
    int biasoff = tb ? 640 + (xt - 5) * 128 : xt * 128;
    int row0 = blockIdx.y << 7;
    if (row0 >= M) return;

    float acc[4][4][4] = {};
    gemm_tile<false>(smem, sb, A + (size_t)row0 * 128, 128, M - row0,
                     wblob + (size_t)xt * 32768, acc);

    int lane = threadIdx.x & 31, wid = threadIdx.x >> 5;
    int warp_m = wid & 1, warp_n = wid >> 1;
    int crow = lane >> 2, ccol = (lane & 3) * 2;
#pragma unroll
    for (int nt = 0; nt < 4; nt++) {
        int nl = warp_n * 32 + nt * 8 + ccol;
        float b0 = bias[biasoff + nl], b1 = bias[biasoff + nl + 1];
#pragma unroll
        for (int mt = 0; mt < 4; mt++) {
            int m = row0 + warp_m * 64 + mt * 16 + crow;
            if (m < M) {
                float2 o = make_float2(acc[mt][nt][0] + b0, acc[mt][nt][1] + b1);
                *(float2*)(C + (size_t)m * ldc + coloff + nl) = o;
            }
            if (m + 8 < M) {
                float2 o = make_float2(acc[mt][nt][2] + b0, acc[mt][nt][3] + b1);
                *(float2*)(C + (size_t)(m + 8) * ldc + coloff + nl) = o;
            }
        }
    }
}

// ---------------------------------------------------------------------------
// Merged out GEMM + skip/[LN]/gelu epilogue.
// ---------------------------------------------------------------------------
template <int EPI>
__global__ void __launch_bounds__(256)
k_gemm_out(const float* __restrict__ agg, int Ma, int Mb, int mtA,
           const __nv_bfloat16* __restrict__ wblob, const float* __restrict__ bias2,
           float* __restrict__ hbuf,
           const float* __restrict__ ssa, const float* __restrict__ ssb,
           const float* __restrict__ skip2,
           const float* __restrict__ lng, const float* __restrict__ lnb) {
    extern __shared__ __align__(128) char smem[];
    uint32_t sb = smem_u32(smem);
    int yt = blockIdx.y;
    bool tb = yt >= mtA;
    int row0 = (tb ? yt - mtA : yt) << 7;
    int M = tb ? Mb : Ma;
    if (row0 >= M) return;
    const float* A = agg + (tb ? (size_t)Ma * 128 : 0);
    const __nv_bfloat16* blob = wblob + (tb ? 32768 : 0);
    const float* bias = bias2 + (tb ? 128 : 0);
    float* C = hbuf + (tb ? (size_t)Ma * 128 : 0);
    const float* ssrc = tb ? ssb : ssa;
    const float* lg = lng + (tb ? 128 : 0);
    const float* lb = lnb + (tb ? 128 : 0);

    float acc[4][4][4] = {};
    gemm_tile<true>(smem, sb, A + (size_t)row0 * 128, 128, M - row0, blob, acc);

    int tid = threadIdx.x, lane = tid & 31, wid = tid >> 5;
    int warp_m = wid & 1, warp_n = wid >> 1;
    int crow = lane >> 2, ccol = (lane & 3) * 2;

    float sg = 1.f / (1.f + expf(-skip2[tb ? 1 : 0]));
#pragma unroll
    for (int nt = 0; nt < 4; nt++) {
        int nl = warp_n * 32 + nt * 8 + ccol;
        float b0 = bias[nl], b1 = bias[nl + 1];
#pragma unroll
        for (int mt = 0; mt < 4; mt++) {
            int m = row0 + warp_m * 64 + mt * 16 + crow;
            if (m < M) {
                float2 h0 = *(const float2*)(ssrc + (size_t)m * 128 + nl);
                acc[mt][nt][0] = sg * (acc[mt][nt][0] + b0) + (1.f - sg) * h0.x;
                acc[mt][nt][1] = sg * (acc[mt][nt][1] + b1) + (1.f - sg) * h0.y;
            }
            if (m + 8 < M) {
                float2 h1 = *(const float2*)(ssrc + (size_t)(m + 8) * 128 + nl);
                acc[mt][nt][2] = sg * (acc[mt][nt][2] + b0) + (1.f - sg) * h1.x;
                acc[mt][nt][3] = sg * (acc[mt][nt][3] + b1) + (1.f - sg) * h1.y;
            }
        }
    }
    if (EPI == 2) {
        float* ssum = (float*)smem;
        float* ssq  = ssum + 128;
        if (tid < 128) { ssum[tid] = 0.f; ssq[tid] = 0.f; }
        __syncthreads();
#pragma unroll
        for (int mt = 0; mt < 4; mt++) {
#pragma unroll
            for (int half = 0; half < 2; half++) {
                float p = 0.f, q = 0.f;
#pragma unroll
                for (int nt = 0; nt < 4; nt++) {
                    float v0 = acc[mt][nt][half * 2];
                    float v1 = acc[mt][nt][half * 2 + 1];
                    p += v0 + v1; q += v0 * v0 + v1 * v1;
                }
                p += __shfl_xor_sync(~0u, p, 1); q += __shfl_xor_sync(~0u, q, 1);
                p += __shfl_xor_sync(~0u, p, 2); q += __shfl_xor_sync(~0u, q, 2);
                if ((lane & 3) == 0) {
                    int row = warp_m * 64 + mt * 16 + half * 8 + crow;
                    atomicAdd(&ssum[row], p);
                    atomicAdd(&ssq[row], q);
                }
            }
        }
        __syncthreads();
#pragma unroll
        for (int mt = 0; mt < 4; mt++) {
            int r0 = warp_m * 64 + mt * 16 + crow;
            float mu0 = ssum[r0] * 0.0078125f;
            float rs0 = rsqrtf(ssq[r0] * 0.0078125f - mu0 * mu0 + 1e-5f);
            float mu1 = ssum[r0 + 8] * 0.0078125f;
            float rs1 = rsqrtf(ssq[r0 + 8] * 0.0078125f - mu1 * mu1 + 1e-5f);
            int m = row0 + r0;
#pragma unroll
            for (int nt = 0; nt < 4; nt++) {
                int nl = warp_n * 32 + nt * 8 + ccol;
                float g0 = lg[nl], g1 = lg[nl + 1];
                float e0 = lb[nl], e1 = lb[nl + 1];
                if (m < M) {
                    float2 o;
                    o.x = gelu_f((acc[mt][nt][0] - mu0) * rs0 * g0 + e0);
                    o.y = gelu_f((acc[mt][nt][1] - mu0) * rs0 * g1 + e1);
                    *(float2*)(C + (size_t)m * 128 + nl) = o;
                }
                if (m + 8 < M) {
                    float2 o;
                    o.x = gelu_f((acc[mt][nt][2] - mu1) * rs1 * g0 + e0);
                    o.y = gelu_f((acc[mt][nt][3] - mu1) * rs1 * g1 + e1);
                    *(float2*)(C + (size_t)(m + 8) * 128 + nl) = o;
                }
            }
        }
    } else {
#pragma unroll
        for (int nt = 0; nt < 4; nt++) {
            int nl = warp_n * 32 + nt * 8 + ccol;
#pragma unroll
            for (int mt = 0; mt < 4; mt++) {
                int m = row0 + warp_m * 64 + mt * 16 + crow;
                if (m < M) {
                    float2 o = make_float2(gelu_f(acc[mt][nt][0]), gelu_f(acc[mt][nt][1]));
                    *(float2*)(C + (size_t)m * 128 + nl) = o;
                }
                if (m + 8 < M) {
                    float2 o = make_float2(gelu_f(acc[mt][nt][2]), gelu_f(acc[mt][nt][3]));
                    *(float2*)(C + (size_t)(m + 8) * 128 + nl) = o;
                }
            }
        }
    }
}

// ---------------------------------------------------------------------------
// CSR build
// ---------------------------------------------------------------------------
__global__ void k_zero_deg(int* d, int n) {
    int i = blockIdx.x * blockDim.x + threadIdx.x;
    if (i < n) d[i] = 0;
}
__global__ void k_count(const int* __restrict__ aa, const int* __restrict__ ab,
                        const int* __restrict__ ba, int* __restrict__ deg, int E, int Na) {
    int i = blockIdx.x * blockDim.x + threadIdx.x;
    if (i >= 3 * E) return;
    int dst;
    if (i < E) dst = aa[E + i];
    else if (i < 2 * E) dst = ab[E + (i - E)] + Na;
    else dst = ba[E + (i - 2 * E)];
    atomicAdd(&deg[dst + 1], 1);
}
__global__ void k_scan1(const int* __restrict__ deg, int* __restrict__ rowptr,
                        int* __restrict__ bsum, int n) {
    __shared__ int buf[1024];
    int i = blockIdx.x * 1024 + threadIdx.x;
    int v = (i < n) ? deg[i] : 0;
    buf[threadIdx.x] = v;
    __syncthreads();
    for (int o = 1; o < 1024; o <<= 1) {
        int u = (threadIdx.x >= o) ? buf[threadIdx.x - o] : 0;
        __syncthreads();
        buf[threadIdx.x] += u;
        __syncthreads();
    }
    if (i < n) rowptr[i] = buf[threadIdx.x];
    if (threadIdx.x == 1023) bsum[blockIdx.x] = buf[1023];
}
__global__ void k_scan2(int* __restrict__ bsum, int nb) {
    __shared__ int s[64];
    int t = threadIdx.x;
    int v = (t < nb) ? bsum[t] : 0;
    s[t] = v;
    __syncthreads();
    for (int o = 1; o < 64; o <<= 1) {
        int u = (t >= o) ? s[t - o] : 0;
        __syncthreads();
        s[t] += u;
        __syncthreads();
    }
    if (t < nb) bsum[t] = s[t] - v;   // exclusive
}
__global__ void k_scan3(const int* __restrict__ bsum, int* __restrict__ rowptr,
                        int* __restrict__ cursor, int n, int N) {
    int i = blockIdx.x * blockDim.x + threadIdx.x;
    if (i >= n) return;
    int v = rowptr[i] + bsum[i >> 10];
    rowptr[i] = v;
    if (i < N) cursor[i] = v;
}
__global__ void k_fill(const int* __restrict__ aa, const int* __restrict__ ab,
                       const int* __restrict__ ba, int* __restrict__ cursor,
                       int* __restrict__ cse, int E, int Na) {
    int i = blockIdx.x * blockDim.x + threadIdx.x;
    if (i >= 3 * E) return;
    int src, dst, et;
    if (i < E)            { et = 0; src = aa[i]; dst = aa[E + i]; }
    else if (i < 2 * E)   { et = 1; int j = i - E;     src = ab[j]; dst = ab[E + j] + Na; }
    else                  { et = 2; int j = i - 2 * E; src = ba[j]; dst = ba[E + j]; }
    int pos = atomicAdd(&cursor[dst], 1);
    cse[pos] = src | (et << 29);
}

// ---------------------------------------------------------------------------
// Fused HGT edge online-softmax aggregate. One warp per dst node.
// Depth-1 pipeline + fast exp in the loop-carried softmax chain.
// ---------------------------------------------------------------------------
__global__ void k_hgt_edges(const float* __restrict__ fa, const float* __restrict__ fb,
                            const int* __restrict__ rowptr, const int* __restrict__ cse,
                            const float* __restrict__ prelL,
                            float* __restrict__ agg, int Na, int N) {
    __shared__ float sp[12];
    if (threadIdx.x < 12) sp[threadIdx.x] = prelL[threadIdx.x];
    __syncthreads();
    int warp = (blockIdx.x * blockDim.x + threadIdx.x) >> 5;
    int lane = threadIdx.x & 31;
    if (warp >= N) return;
    int n = warp;
    const float* qrow = (n < Na) ? (fa + (size_t)n * 640) : (fb + (size_t)(n - Na) * 384);
    float4 q4 = *(const float4*)(qrow + lane * 4);
    int h = lane >> 3;
    int beg = rowptr[n], end = rowptr[n + 1];

    float mx = -INFINITY, sum = 0.f;
    float4 acc = make_float4(0.f, 0.f, 0.f, 0.f);

    int idx = beg;
    int p0 = (idx < end) ? cse[idx] : 0;
    int p1 = (idx + 1 < end) ? cse[idx + 1] : 0;
    float4 k4 = {}, v4 = {};
    if (idx < end) {
        int et = p0 >> 29, src = p0 & 0x1FFFFFFF;
        const float* base = (et < 2) ? (fa + (size_t)src * 640 + 128 + (et << 8))
                                     : (fb + (size_t)src * 384 + 128);
        k4 = *(const float4*)(base + lane * 4);
        v4 = *(const float4*)(base + 128 + lane * 4);
    }
    while (idx < end) {
        // prefetch next k/v from already-resident p1; load p2 in parallel
        int p2 = (idx + 2 < end) ? cse[idx + 2] : 0;
        float4 k4n = {}, v4n = {};
        if (idx + 1 < end) {
            int etn = p1 >> 29, srcn = p1 & 0x1FFFFFFF;
            const float* basen = (etn < 2) ? (fa + (size_t)srcn * 640 + 128 + (etn << 8))
                                           : (fb + (size_t)srcn * 384 + 128);
            k4n = *(const float4*)(basen + lane * 4);
            v4n = *(const float4*)(basen + 128 + lane * 4);
        }
        int et = p0 >> 29;
        float s = q4.x * k4.x + q4.y * k4.y + q4.z * k4.z + q4.w * k4.w;
        s += __shfl_xor_sync(0xffffffffu, s, 1);
        s += __shfl_xor_sync(0xffffffffu, s, 2);
        s += __shfl_xor_sync(0xffffffffu, s, 4);
        float lg = s * sp[et * 4 + h] * 0.17677669529663687f;  // /sqrt(32)
        float mnew = fmaxf(mx, lg);
        float corr = __expf(mx - mnew);    // 0 on first edge (mx=-inf)
        float w = __expf(lg - mnew);
        sum = sum * corr + w;
        acc.x = acc.x * corr + w * v4.x;
        acc.y = acc.y * corr + w * v4.y;
        acc.z = acc.z * corr + w * v4.z;
        acc.w = acc.w * corr + w * v4.w;
        mx = mnew;
        p0 = p1; p1 = p2; k4 = k4n; v4 = v4n; idx++;
    }
    float inv = 1.f / (sum + 1e-16f);
    acc.x *= inv; acc.y *= inv; acc.z *= inv; acc.w *= inv;
    *(float4*)(agg + (size_t)n * 128 + lane * 4) = acc;
}

// ---------------------------------------------------------------------------
// GAT scorer via CSR (+analytic self loops), online softmax, one pass.
// Depth-1 index pipeline + fast exp.
// ---------------------------------------------------------------------------
__global__ void k_x1(const float* __restrict__ h, const float* __restrict__ Wg,
                     float* __restrict__ x1, int N) {
    int gw = (blockIdx.x * blockDim.x + threadIdx.x) >> 5;
    int lane = threadIdx.x & 31;
    if (gw >= N) return;
    const float* row = h + (size_t)gw * 128;
    float v = row[lane] * Wg[lane] + row[32 + lane] * Wg[32 + lane]
            + row[64 + lane] * Wg[64 + lane] + row[96 + lane] * Wg[96 + lane];
    v += __shfl_down_sync(0xffffffffu, v, 16);
    v += __shfl_down_sync(0xffffffffu, v, 8);
    v += __shfl_down_sync(0xffffffffu, v, 4);
    v += __shfl_down_sync(0xffffffffu, v, 2);
    v += __shfl_down_sync(0xffffffffu, v, 1);
    if (lane == 0) x1[gw] = v;
}

__global__ void k_gat(const float* __restrict__ x1, const int* __restrict__ rowptr,
                      const int* __restrict__ cse, const float* __restrict__ as_,
                      const float* __restrict__ ad_, const float* __restrict__ bg,
                      float* __restrict__ score, int Na, int N) {
    int n = blockIdx.x * blockDim.x + threadIdx.x;
    if (n >= N) return;
    float a_s = as_[0], a_d = ad_[0];
    float xd = x1[n];
    float eself = xd * (a_s + a_d);
    eself = eself > 0.f ? eself : 0.2f * eself;
    float m = eself, sum = 1.f, num = xd;    // self loop: w=exp(0)=1
    int beg = rowptr[n], end = rowptr[n + 1];

    int i = beg;
    int p0 = (i < end) ? cse[i] : 0;
    float xs = 0.f;
    if (i < end) {
        int src = (p0 & 0x1FFFFFFF) + (((p0 >> 29) == 2) ? Na : 0);
        xs = x1[src];
    }
    while (i < end) {
        int p1 = (i + 1 < end) ? cse[i + 1] : 0;
        float xsn = 0.f;
        if (i + 1 < end) {
            int srcn = (p1 & 0x1FFFFFFF) + (((p1 >> 29) == 2) ? Na : 0);
            xsn = x1[srcn];
        }
        float e = xs * a_s + xd * a_d;
        e = e > 0.f ? e : 0.2f * e;
        float mnew = fmaxf(m, e);
        float corr = __expf(m - mnew);
        float w = __expf(e - mnew);
        sum = sum * corr + w;
        num = num * corr + w * xs;
        m = mnew;
        p0 = p1; xs = xsn; i++;
    }
    score[n] = num / (sum + 1e-16f) + bg[0];
}

// ---------------------------------------------------------------------------
// Top-K prepass: each block emits its local top-8 (val desc, idx asc)
// ---------------------------------------------------------------------------
__global__ void k_topk(const float* __restrict__ score, float* __restrict__ cval,
                       int* __restrict__ cidx, int N) {
    const float NEG_INF = __int_as_float(0xff800000);
    __shared__ float sval[256];
    __shared__ int   sida[256];
    __shared__ float sred[256];
    __shared__ int   sidr[256];
    int t = threadIdx.x;
    int i = blockIdx.x * 256 + t;
    sval[t] = (i < N) ? score[i] : NEG_INF;
    sida[t] = (i < N) ? i : 0x7fffffff;
    __syncthreads();
    for (int k = 0; k < 8; k++) {
        sred[t] = sval[t]; sidr[t] = sida[t];
        __syncthreads();
        for (int s = 128; s > 0; s >>= 1) {
            if (t < s) {
                if (sred[t + s] > sred[t] ||
                    (sred[t + s] == sred[t] && sidr[t + s] < sidr[t])) {
                    sred[t] = sred[t + s]; sidr[t] = sidr[t + s];
                }
            }
            __syncthreads();
        }
        int win = sidr[0];
        if (t == 0) {
            cval[blockIdx.x * 8 + k] = sred[0];
            cidx[blockIdx.x * 8 + k] = win;
        }
        if (sida[t] == win) sval[t] = NEG_INF;
        __syncthreads();
    }
}

// ---------------------------------------------------------------------------
// Final: global top-8 from candidates, gated readout, 3-layer MLP, nan_to_num.
// ---------------------------------------------------------------------------
__global__ void k_final(const float* __restrict__ h,
                        const float* __restrict__ cval, const int* __restrict__ cidx,
                        int ncand,
                        const float* __restrict__ W1, const float* __restrict__ b1,
                        const float* __restrict__ W2, const float* __restrict__ b2,
                        const float* __restrict__ W3, const float* __restrict__ b3,
                        float* __restrict__ out) {
    const float NEG_INF = __int_as_float(0xff800000);
    __shared__ float cv[MAXCAND];
    __shared__ int   ci[MAXCAND];
    __shared__ float sred[256];
    __shared__ int   sidx[256];
    __shared__ float hp[1024];
    __shared__ int   perm[8];
    __shared__ float vals[8];
    __shared__ float v1[128];
    __shared__ float v2[64];
    int t = threadIdx.x;

    for (int i = t; i < MAXCAND; i += 256) {
        cv[i] = (i < ncand) ? cval[i] : NEG_INF;
        ci[i] = (i < ncand) ? cidx[i] : 0x7fffffff;
    }
    __syncthreads();

    for (int k = 0; k < 8; k++) {
        float bv = NEG_INF; int bi = 0x7fffffff;
        for (int i = t; i < MAXCAND; i += 256) {
            float v = cv[i];
            if (v > bv || (v == bv && ci[i] < bi)) { bv = v; bi = ci[i]; }
        }
        sred[t] = bv; sidx[t] = bi;
        __syncthreads();
        for (int s = 128; s > 0; s >>= 1) {
            if (t < s) {
                if (sred[t + s] > sred[t] ||
                    (sred[t + s] == sred[t] && sidx[t + s] < sidx[t])) {
                    sred[t] = sred[t + s]; sidx[t] = sidx[t + s];
                }
            }
            __syncthreads();
        }
        int win = sidx[0];
        if (t == 0) { perm[k] = win; vals[k] = sred[0]; }
        for (int i = t; i < MAXCAND; i += 256)
            if (ci[i] == win) cv[i] = NEG_INF;
        __syncthreads();
    }

    for (int i = t; i < 1024; i += 256) {
        int k = i >> 7, j = i & 127;
        hp[i] = h[(size_t)perm[k] * 128 + j] * tanhf(vals[k]);
    }
    __syncthreads();

    if (t < 128) {
        float acc = b1[t];
        for (int i = 0; i < 1024; i++) acc += hp[i] * W1[i * 128 + t];
        v1[t] = gelu_f(acc);
    }
    __syncthreads();
    if (t < 64) {
        float acc = b2[t];
        for (int i = 0; i < 128; i++) acc += v1[i] * W2[i * 64 + t];
        v2[t] = gelu_f(acc);
    }
    __syncthreads();
    if (t < 16) {
        float acc = b3[t];
        for (int i = 0; i < 64; i++) acc += v2[i] * W3[i * 16 + t];
        float r = gelu_f(acc);
        if (isnan(r)) r = 0.f;
        else if (isinf(r)) r = (r > 0.f) ? 3.4028234663852886e38f : -3.4028234663852886e38f;
        out[t] = r;
    }
}

// ---------------------------------------------------------------------------
static inline int cdiv(int a, int b) { return (a + b - 1) / b; }

extern "C" void kernel_launch(void* const* d_in, const int* in_sizes, int n_in,
                              void* d_out, int out_size) {
    const float* x_a   = (const float*)d_in[0];
    const float* x_b   = (const float*)d_in[1];
    const int*   ei_aa = (const int*)d_in[2];
    const int*   ei_ab = (const int*)d_in[3];
    const int*   ei_ba = (const int*)d_in[4];
    const float* Wkqv  = (const float*)d_in[5];
    const float* bkqv  = (const float*)d_in[6];
    const float* Wout  = (const float*)d_in[7];
    const float* bout  = (const float*)d_in[8];
    const float* skip  = (const float*)d_in[9];
    const float* arel  = (const float*)d_in[10];
    const float* mrel  = (const float*)d_in[11];
    const float* prel  = (const float*)d_in[12];
    const float* ln_g  = (const float*)d_in[13];
    const float* ln_b  = (const float*)d_in[14];
    const float* Wgat  = (const float*)d_in[15];
    const float* att_s = (const float*)d_in[16];
    const float* att_d = (const float*)d_in[17];
    const float* bgat  = (const float*)d_in[18];
    const float* W1    = (const float*)d_in[19];
    const float* b1    = (const float*)d_in[20];
    const float* W2    = (const float*)d_in[21];
    const float* b2    = (const float*)d_in[22];
    const float* W3    = (const float*)d_in[23];
    const float* b3    = (const float*)d_in[24];

    int Na = in_sizes[0] / 128;
    int Nb = in_sizes[1] / 128;
    int N  = Na + Nb;
    int E  = in_sizes[2] / 2;

    float *hbuf, *fa, *fb, *bcat, *aggb, *x1b, *scoreb, *cvalb;
    __nv_bfloat16 *wAb, *wOb;
    int *degb, *rowptrb, *cursorb, *cseb, *bsumb, *cidxb;
    cudaGetSymbolAddress((void**)&hbuf, g_h);
    cudaGetSymbolAddress((void**)&fa, g_feat_a);
    cudaGetSymbolAddress((void**)&fb, g_feat_b);
    cudaGetSymbolAddress((void**)&bcat, g_bcat);
    cudaGetSymbolAddress((void**)&wAb, g_wA);
    cudaGetSymbolAddress((void**)&wOb, g_wO);
    cudaGetSymbolAddress((void**)&aggb, g_agg);
    cudaGetSymbolAddress((void**)&degb, g_deg);
    cudaGetSymbolAddress((void**)&rowptrb, g_rowptr);
    cudaGetSymbolAddress((void**)&cursorb, g_cursor);
    cudaGetSymbolAddress((void**)&cseb, g_cse);
    cudaGetSymbolAddress((void**)&bsumb, g_bsum);
    cudaGetSymbolAddress((void**)&x1b, g_x1);
    cudaGetSymbolAddress((void**)&scoreb, g_score);
    cudaGetSymbolAddress((void**)&cvalb, g_cval);
    cudaGetSymbolAddress((void**)&cidxb, g_cidx);

    cudaFuncSetAttribute(k_gemm_feat,   cudaFuncAttributeMaxDynamicSharedMemorySize, SMEM_GEMM);
    cudaFuncSetAttribute(k_gemm_out<1>, cudaFuncAttributeMaxDynamicSharedMemorySize, SMEM_GEMM);
    cudaFuncSetAttribute(k_gemm_out<2>, cudaFuncAttributeMaxDynamicSharedMemorySize, SMEM_GEMM);

    // CSR build + weight fold/prep (reused across layers)
    int n1 = N + 1;
    int nbk = cdiv(n1, 1024);
    k_zero_deg<<<cdiv(n1, 256), 256>>>(degb, n1);
    k_count<<<cdiv(3 * E, 256), 256>>>(ei_aa, ei_ab, ei_ba, degb, E, Na);
    k_scan1<<<nbk, 1024>>>(degb, rowptrb, bsumb, n1);
    k_scan2<<<1, 64>>>(bsumb, nbk);
    k_scan3<<<cdiv(n1, 256), 256>>>(bsumb, rowptrb, cursorb, n1, N);
    k_fill<<<cdiv(3 * E, 256), 256>>>(ei_aa, ei_ab, ei_ba, cursorb, cseb, E, Na);
    k_fold2<<<cdiv(30 * 16384 + 3 * 1024, 256), 256>>>(Wkqv, bkqv, Wout, arel, mrel,
                                                       wAb, wOb, bcat);

    int mbA = cdiv(Na, 128), mbB = cdiv(Nb, 128);
    int mbMax = mbA > mbB ? mbA : mbB;

    for (int L = 0; L < 3; L++) {
        const float* Aa = (L == 0) ? x_a : hbuf;
        const float* Ab = (L == 0) ? x_b : hbuf + (size_t)Na * 128;
        k_gemm_feat<<<dim3(8, mbMax), 256, SMEM_GEMM>>>(
            Aa, Ab, Na, Nb, wAb + (size_t)L * 8 * 32768, bcat + L * 1024, fa, fb);
        k_hgt_edges<<<cdiv(N * 32, 256), 256>>>(fa, fb, rowptrb, cseb,
            prel + L * 12, aggb, Na, N);
        if (L == 0) {
            k_gemm_out<2><<<dim3(1, mbA + mbB), 256, SMEM_GEMM>>>(
                aggb, Na, Nb, mbA, wOb + (size_t)L * 2 * 32768, bout + L * 2 * 128,
                hbuf, x_a, x_b, skip + L * 2, ln_g, ln_b);
        } else {
            k_gemm_out<1><<<dim3(1, mbA + mbB), 256, SMEM_GEMM>>>(
                aggb, Na, Nb, mbA, wOb + (size_t)L * 2 * 32768, bout + L * 2 * 128,
                hbuf, hbuf, hbuf + (size_t)Na * 128, skip + L * 2, ln_g, ln_b);
        }
    }

    // GAT scorer + SAGPool + MLP
    k_x1<<<cdiv(N * 32, 256), 256>>>(hbuf, Wgat, x1b, N);
    k_gat<<<cdiv(N, 256), 256>>>(x1b, rowptrb, cseb, att_s, att_d, bgat, scoreb, Na, N);
    int nblk = cdiv(N, 256);
    k_topk<<<nblk, 256>>>(scoreb, cvalb, cidxb, N);
    k_final<<<1, 256>>>(hbuf, cvalb, cidxb, nblk * 8,
                        W1, b1, W2, b2, W3, b3, (float*)d_out);
}

// round 17
// speedup vs baseline: 1.0179x; 1.0179x over previous
#include <cuda_runtime.h>
#include <cuda_bf16.h>
#include <math.h>
#include <stdint.h>

#define NAC 20000
#define NBC 20000
#define NNC 40000
#define EC  150000
#define MAXCAND 2048

// ---------------------------------------------------------------------------
// Scratch (static device globals)
// ---------------------------------------------------------------------------
__device__ float g_h[NNC * 128];             // node features [a;b]
__device__ float g_feat_a[NAC * 640];        // q|kt0|vt0|kt1|vt1 for type a
__device__ float g_feat_b[NBC * 384];        // q|kt2|vt2 for type b
__device__ float g_bcat[3 * 1024];           // folded biases
__device__ __align__(16) __nv_bfloat16 g_wA[24 * 32768];  // split/swizzled wcat tiles
__device__ __align__(16) __nv_bfloat16 g_wO[6 * 32768];   // split/swizzled Wout tiles
__device__ float g_agg[NNC * 128];
__device__ int   g_deg[NNC + 1];
__device__ int   g_rowptr[NNC + 1];
__device__ int   g_cursor[NNC];
__device__ int   g_bsum[64];
__device__ int   g_cse[3 * EC];              // src | et<<29
__device__ float g_x1[NNC];
__device__ float g_score[NNC];
__device__ float g_cval[MAXCAND];
__device__ int   g_cidx[MAXCAND];

__device__ __forceinline__ float gelu_f(float x) {
    return 0.5f * x * (1.0f + erff(x * 0.7071067811865475f));
}
__device__ __forceinline__ uint32_t smem_u32(const void* p) {
    uint32_t a;
    asm("{ .reg .u64 t; cvta.to.shared.u64 t, %1; cvt.u32.u64 %0, t; }" : "=r"(a) : "l"(p));
    return a;
}
__device__ __forceinline__ void mma_bf16(float* c, const uint32_t* a, const uint32_t* b) {
    asm volatile(
        "mma.sync.aligned.m16n8k16.row.col.f32.bf16.bf16.f32 "
        "{%0,%1,%2,%3}, {%4,%5,%6,%7}, {%8,%9}, {%0,%1,%2,%3};"
        : "+f"(c[0]), "+f"(c[1]), "+f"(c[2]), "+f"(c[3])
        : "r"(a[0]), "r"(a[1]), "r"(a[2]), "r"(a[3]), "r"(b[0]), "r"(b[1]));
}
__device__ __forceinline__ void ldsm_x4(uint32_t* r, uint32_t addr) {
    asm volatile("ldmatrix.sync.aligned.m8n8.x4.shared.b16 {%0,%1,%2,%3}, [%4];"
                 : "=r"(r[0]), "=r"(r[1]), "=r"(r[2]), "=r"(r[3]) : "r"(addr));
}
#define CP_ASYNC16(dst, src) \
    asm volatile("cp.async.cg.shared.global [%0], [%1], 16;" :: "r"(dst), "l"(src))
#define CP_COMMIT() asm volatile("cp.async.commit_group;" ::: "memory")
#define CP_WAIT0()  asm volatile("cp.async.wait_group 0;" ::: "memory")

// split 8 consecutive floats into packed bf16 hi (16B) and lo (16B)
__device__ __forceinline__ void split8(const float* f, uint4& hi, uint4& lo) {
    uint32_t h[4], l[4];
#pragma unroll
    for (int j = 0; j < 4; j++) {
        float f0 = f[2 * j], f1 = f[2 * j + 1];
        __nv_bfloat16 b0 = __float2bfloat16_rn(f0);
        __nv_bfloat16 b1 = __float2bfloat16_rn(f1);
        float r0 = f0 - __bfloat162float(b0);
        float r1 = f1 - __bfloat162float(b1);
        __nv_bfloat162 hh = __halves2bfloat162(b0, b1);
        __nv_bfloat162 ll = __halves2bfloat162(__float2bfloat16_rn(r0),
                                               __float2bfloat16_rn(r1));
        h[j] = *(uint32_t*)&hh;
        l[j] = *(uint32_t*)&ll;
    }
    hi = make_uint4(h[0], h[1], h[2], h[3]);
    lo = make_uint4(l[0], l[1], l[2], l[3]);
}

// ---------------------------------------------------------------------------
// Folded weight value (q | per-edge-type kt/vt). i==128 -> bias.
// ---------------------------------------------------------------------------
__device__ float fold_val(const float* __restrict__ Wkqv, const float* __restrict__ bkqv,
                          const float* __restrict__ arel, const float* __restrict__ mrel,
                          int L, int i, int c) {
    int type = (c >= 640) ? 1 : 0;
    int cc = c - (type ? 640 : 0);
    int part = cc >> 7, wi = cc & 127;
    const float* Wrow = (i < 128) ? Wkqv + ((size_t)(L * 2 + type) * 128 + i) * 384
                                  : bkqv + (size_t)(L * 2 + type) * 384;
    if (part == 0) return Wrow[128 + wi];
    int et, kv;
    if (type == 0) { et = (part - 1) >> 1; kv = (part - 1) & 1; }
    else           { et = 2;               kv = part - 1; }
    int h = wi >> 5, e2 = wi & 31;
    const float* rel = (kv ? mrel : arel) + ((size_t)(L * 3 + et) * 4 + h) * 1024 + e2;
    const float* ws = Wrow + (kv ? 256 : 0) + h * 32;
    float s = 0.f;
#pragma unroll
    for (int d = 0; d < 32; d++) s += ws[d] * rel[d * 32];
    return s;
}

__global__ void k_fold2(const float* __restrict__ Wkqv, const float* __restrict__ bkqv,
                        const float* __restrict__ Wout,
                        const float* __restrict__ arel, const float* __restrict__ mrel,
                        __nv_bfloat16* __restrict__ wA, __nv_bfloat16* __restrict__ wO,
                        float* __restrict__ bcat) {
    int idx = blockIdx.x * blockDim.x + threadIdx.x;
    const int PER = 16384;
    const int WTOT = 30 * PER;
    if (idx < WTOT) {
        int t = idx / PER, e = idx % PER;
        int k = e >> 7, n = e & 127;
        float v;
        __nv_bfloat16* dst;
        if (t < 24) {
            int L = t >> 3, xt = t & 7;
            int c = (xt < 5) ? xt * 128 + n : 640 + (xt - 5) * 128 + n;
            v = fold_val(Wkqv, bkqv, arel, mrel, L, k, c);
            dst = wA + (size_t)t * 32768;
        } else {
            v = Wout[(size_t)(t - 24) * 16384 + k * 128 + n];
            dst = wO + (size_t)(t - 24) * 32768;
        }
        __nv_bfloat16 hi = __float2bfloat16_rn(v);
        __nv_bfloat16 lo = __float2bfloat16_rn(v - __bfloat162float(hi));
        int chunk = k >> 6, kk = k & 63;
        int ksw = ((kk * 2) ^ ((n & 7) << 4)) >> 1;
        dst += chunk * 16384;
        dst[n * 64 + ksw] = hi;
        dst[8192 + n * 64 + ksw] = lo;
    } else if (idx < WTOT + 3 * 1024) {
        int j = idx - WTOT;
        int L = j >> 10, c = j & 1023;
        bcat[L * 1024 + c] = fold_val(Wkqv, bkqv, arel, mrel, L, 128, c);
    }
}

// ---------------------------------------------------------------------------
// GEMM core: 128x128 tile, acc = bf16-2split(A) @ Wtile. 8 warps (2M x 4N).
// (Frozen: single-buffered, 64KB smem, regs=128, 2 CTA/SM.)
// ---------------------------------------------------------------------------
#define SMEM_GEMM 65536
template <bool GELU_A>
__device__ __forceinline__ void gemm_tile(char* smem, uint32_t sb,
                                          const float* __restrict__ A, int lda, int arows,
                                          const __nv_bfloat16* __restrict__ blob,
                                          float acc[4][4][4]) {
    const int AHI = 0, ALO = 16384, BHI = 32768;
    int tid = threadIdx.x, lane = tid & 31, wid = tid >> 5;
    int warp_m = wid & 1, warp_n = wid >> 1;
    int lm = lane & 15;
    int lk = (lane >> 4) << 4;

    for (int chunk = 0; chunk < 2; chunk++) {
        {
            const char* src = (const char*)(blob + chunk * 16384);
            uint32_t dst = sb + BHI;
#pragma unroll
            for (int it = 0; it < 8; it++) {
                int i = it * 256 + tid;
                CP_ASYNC16(dst + i * 16, src + i * 16);
            }
            CP_COMMIT();
        }
#pragma unroll
        for (int it = 0; it < 4; it++) {
            int i = it * 256 + tid;
            int m = i >> 3, kg = i & 7;
            float f[8] = {};
            if (m < arows) {
                const float* ap = A + (size_t)m * lda + chunk * 64 + kg * 8;
                *(float4*)&f[0] = *(const float4*)ap;
                *(float4*)&f[4] = *(const float4*)(ap + 4);
            }
            if (GELU_A) {
#pragma unroll
                for (int j = 0; j < 8; j++) f[j] = gelu_f(f[j]);
            }
            uint4 hi, lo;
            split8(f, hi, lo);
            int off = m * 128 + ((kg * 16) ^ ((m & 7) << 4));
            *(uint4*)(smem + AHI + off) = hi;
            *(uint4*)(smem + ALO + off) = lo;
        }
        CP_WAIT0();
        __syncthreads();

#pragma unroll
        for (int k16 = 0; k16 < 4; k16++) {
            int kb = k16 * 32 + lk;
            uint32_t bh[2][4], bl[2][4];
#pragma unroll
            for (int ntp = 0; ntp < 2; ntp++) {
                int n = warp_n * 32 + ntp * 16 + lm;
                int off = n * 128 + (kb ^ ((n & 7) << 4));
                ldsm_x4(bh[ntp], sb + BHI + off);
                ldsm_x4(bl[ntp], sb + BHI + 16384 + off);
            }
#pragma unroll
            for (int mt = 0; mt < 4; mt++) {
                int m = warp_m * 64 + mt * 16 + lm;
                int off = m * 128 + (kb ^ ((m & 7) << 4));
                uint32_t ah[4], al[4];
                ldsm_x4(ah, sb + AHI + off);
                ldsm_x4(al, sb + ALO + off);
#pragma unroll
                for (int nt = 0; nt < 4; nt++) {
                    uint32_t bfh[2] = {bh[nt >> 1][nt & 1], bh[nt >> 1][(nt & 1) + 2]};
                    uint32_t bfl[2] = {bl[nt >> 1][nt & 1], bl[nt >> 1][(nt & 1) + 2]};
                    mma_bf16(acc[mt][nt], ah, bfh);
                    mma_bf16(acc[mt][nt], ah, bfl);
                    mma_bf16(acc[mt][nt], al, bfh);
                }
            }
        }
        __syncthreads();
    }
}

// ---------------------------------------------------------------------------
// Merged feature GEMM (both node types in one launch).
// ---------------------------------------------------------------------------
__global__ void __launch_bounds__(256)
k_gemm_feat(const float* __restrict__ Aa, const float* __restrict__ Ab,
            int Ma, int Mb,
            const __nv_bfloat16* __restrict__ wblob, const float* __restrict__ bias,
            float* __restrict__ Ca, float* __restrict__ Cb) {
    extern __shared__ __align__(128) char smem[];
    uint32_t sb = smem_u32(smem);
    int xt = blockIdx.x;
    bool tb = xt >= 5;
    const float* A = tb ? Ab : Aa;
    int M = tb ? Mb : Ma;
    float* C = tb ? Cb : Ca;
    int ldc = tb ? 384 : 640;
    int coloff = tb ? (xt - 5) * 128 : xt * 128;
    int biasoff = tb ? 640 + (xt - 5) * 128 : xt * 128;
    int row0 = blockIdx.y << 7;
    if (row0 >= M) return;

    float acc[4][4][4] = {};
    gemm_tile<false>(smem, sb, A + (size_t)row0 * 128, 128, M - row0,
                     wblob + (size_t)xt * 32768, acc);

    int lane = threadIdx.x & 31, wid = threadIdx.x >> 5;
    int warp_m = wid & 1, warp_n = wid >> 1;
    int crow = lane >> 2, ccol = (lane & 3) * 2;
#pragma unroll
    for (int nt = 0; nt < 4; nt++) {
        int nl = warp_n * 32 + nt * 8 + ccol;
        float b0 = bias[biasoff + nl], b1 = bias[biasoff + nl + 1];
#pragma unroll
        for (int mt = 0; mt < 4; mt++) {
            int m = row0 + warp_m * 64 + mt * 16 + crow;
            if (m < M) {
                float2 o = make_float2(acc[mt][nt][0] + b0, acc[mt][nt][1] + b1);
                *(float2*)(C + (size_t)m * ldc + coloff + nl) = o;
            }
            if (m + 8 < M) {
                float2 o = make_float2(acc[mt][nt][2] + b0, acc[mt][nt][3] + b1);
                *(float2*)(C + (size_t)(m + 8) * ldc + coloff + nl) = o;
            }
        }
    }
}

// ---------------------------------------------------------------------------
// Merged out GEMM + skip/[LN]/gelu epilogue.
// ---------------------------------------------------------------------------
template <int EPI>
__global__ void __launch_bounds__(256)
k_gemm_out(const float* __restrict__ agg, int Ma, int Mb, int mtA,
           const __nv_bfloat16* __restrict__ wblob, const float* __restrict__ bias2,
           float* __restrict__ hbuf,
           const float* __restrict__ ssa, const float* __restrict__ ssb,
           const float* __restrict__ skip2,
           const float* __restrict__ lng, const float* __restrict__ lnb) {
    extern __shared__ __align__(128) char smem[];
    uint32_t sb = smem_u32(smem);
    int yt = blockIdx.y;
    bool tb = yt >= mtA;
    int row0 = (tb ? yt - mtA : yt) << 7;
    int M = tb ? Mb : Ma;
    if (row0 >= M) return;
    const float* A = agg + (tb ? (size_t)Ma * 128 : 0);
    const __nv_bfloat16* blob = wblob + (tb ? 32768 : 0);
    const float* bias = bias2 + (tb ? 128 : 0);
    float* C = hbuf + (tb ? (size_t)Ma * 128 : 0);
    const float* ssrc = tb ? ssb : ssa;
    const float* lg = lng + (tb ? 128 : 0);
    const float* lb = lnb + (tb ? 128 : 0);

    float acc[4][4][4] = {};
    gemm_tile<true>(smem, sb, A + (size_t)row0 * 128, 128, M - row0, blob, acc);

    int tid = threadIdx.x, lane = tid & 31, wid = tid >> 5;
    int warp_m = wid & 1, warp_n = wid >> 1;
    int crow = lane >> 2, ccol = (lane & 3) * 2;

    float sg = 1.f / (1.f + expf(-skip2[tb ? 1 : 0]));
#pragma unroll
    for (int nt = 0; nt < 4; nt++) {
        int nl = warp_n * 32 + nt * 8 + ccol;
        float b0 = bias[nl], b1 = bias[nl + 1];
#pragma unroll
        for (int mt = 0; mt < 4; mt++) {
            int m = row0 + warp_m * 64 + mt * 16 + crow;
            if (m < M) {
                float2 h0 = *(const float2*)(ssrc + (size_t)m * 128 + nl);
                acc[mt][nt][0] = sg * (acc[mt][nt][0] + b0) + (1.f - sg) * h0.x;
                acc[mt][nt][1] = sg * (acc[mt][nt][1] + b1) + (1.f - sg) * h0.y;
            }
            if (m + 8 < M) {
                float2 h1 = *(const float2*)(ssrc + (size_t)(m + 8) * 128 + nl);
                acc[mt][nt][2] = sg * (acc[mt][nt][2] + b0) + (1.f - sg) * h1.x;
                acc[mt][nt][3] = sg * (acc[mt][nt][3] + b1) + (1.f - sg) * h1.y;
            }
        }
    }
    if (EPI == 2) {
        float* ssum = (float*)smem;
        float* ssq  = ssum + 128;
        if (tid < 128) { ssum[tid] = 0.f; ssq[tid] = 0.f; }
        __syncthreads();
#pragma unroll
        for (int mt = 0; mt < 4; mt++) {
#pragma unroll
            for (int half = 0; half < 2; half++) {
                float p = 0.f, q = 0.f;
#pragma unroll
                for (int nt = 0; nt < 4; nt++) {
                    float v0 = acc[mt][nt][half * 2];
                    float v1 = acc[mt][nt][half * 2 + 1];
                    p += v0 + v1; q += v0 * v0 + v1 * v1;
                }
                p += __shfl_xor_sync(~0u, p, 1); q += __shfl_xor_sync(~0u, q, 1);
                p += __shfl_xor_sync(~0u, p, 2); q += __shfl_xor_sync(~0u, q, 2);
                if ((lane & 3) == 0) {
                    int row = warp_m * 64 + mt * 16 + half * 8 + crow;
                    atomicAdd(&ssum[row], p);
                    atomicAdd(&ssq[row], q);
                }
            }
        }
        __syncthreads();
#pragma unroll
        for (int mt = 0; mt < 4; mt++) {
            int r0 = warp_m * 64 + mt * 16 + crow;
            float mu0 = ssum[r0] * 0.0078125f;
            float rs0 = rsqrtf(ssq[r0] * 0.0078125f - mu0 * mu0 + 1e-5f);
            float mu1 = ssum[r0 + 8] * 0.0078125f;
            float rs1 = rsqrtf(ssq[r0 + 8] * 0.0078125f - mu1 * mu1 + 1e-5f);
            int m = row0 + r0;
#pragma unroll
            for (int nt = 0; nt < 4; nt++) {
                int nl = warp_n * 32 + nt * 8 + ccol;
                float g0 = lg[nl], g1 = lg[nl + 1];
                float e0 = lb[nl], e1 = lb[nl + 1];
                if (m < M) {
                    float2 o;
                    o.x = gelu_f((acc[mt][nt][0] - mu0) * rs0 * g0 + e0);
                    o.y = gelu_f((acc[mt][nt][1] - mu0) * rs0 * g1 + e1);
                    *(float2*)(C + (size_t)m * 128 + nl) = o;
                }
                if (m + 8 < M) {
                    float2 o;
                    o.x = gelu_f((acc[mt][nt][2] - mu1) * rs1 * g0 + e0);
                    o.y = gelu_f((acc[mt][nt][3] - mu1) * rs1 * g1 + e1);
                    *(float2*)(C + (size_t)(m + 8) * 128 + nl) = o;
                }
            }
        }
    } else {
#pragma unroll
        for (int nt = 0; nt < 4; nt++) {
            int nl = warp_n * 32 + nt * 8 + ccol;
#pragma unroll
            for (int mt = 0; mt < 4; mt++) {
                int m = row0 + warp_m * 64 + mt * 16 + crow;
                if (m < M) {
                    float2 o = make_float2(gelu_f(acc[mt][nt][0]), gelu_f(acc[mt][nt][1]));
                    *(float2*)(C + (size_t)m * 128 + nl) = o;
                }
                if (m + 8 < M) {
                    float2 o = make_float2(gelu_f(acc[mt][nt][2]), gelu_f(acc[mt][nt][3]));
                    *(float2*)(C + (size_t)(m + 8) * 128 + nl) = o;
                }
            }
        }
    }
}

// ---------------------------------------------------------------------------
// CSR build
// ---------------------------------------------------------------------------
__global__ void k_zero_deg(int* d, int n) {
    int i = blockIdx.x * blockDim.x + threadIdx.x;
    if (i < n) d[i] = 0;
}
__global__ void k_count(const int* __restrict__ aa, const int* __restrict__ ab,
                        const int* __restrict__ ba, int* __restrict__ deg, int E, int Na) {
    int i = blockIdx.x * blockDim.x + threadIdx.x;
    if (i >= 3 * E) return;
    int dst;
    if (i < E) dst = aa[E + i];
    else if (i < 2 * E) dst = ab[E + (i - E)] + Na;
    else dst = ba[E + (i - 2 * E)];
    atomicAdd(&deg[dst + 1], 1);
}
__global__ void k_scan1(const int* __restrict__ deg, int* __restrict__ rowptr,
                        int* __restrict__ bsum, int n) {
    __shared__ int buf[1024];
    int i = blockIdx.x * 1024 + threadIdx.x;
    int v = (i < n) ? deg[i] : 0;
    buf[threadIdx.x] = v;
    __syncthreads();
    for (int o = 1; o < 1024; o <<= 1) {
        int u = (threadIdx.x >= o) ? buf[threadIdx.x - o] : 0;
        __syncthreads();
        buf[threadIdx.x] += u;
        __syncthreads();
    }
    if (i < n) rowptr[i] = buf[threadIdx.x];
    if (threadIdx.x == 1023) bsum[blockIdx.x] = buf[1023];
}
__global__ void k_scan2(int* __restrict__ bsum, int nb) {
    __shared__ int s[64];
    int t = threadIdx.x;
    int v = (t < nb) ? bsum[t] : 0;
    s[t] = v;
    __syncthreads();
    for (int o = 1; o < 64; o <<= 1) {
        int u = (t >= o) ? s[t - o] : 0;
        __syncthreads();
        s[t] += u;
        __syncthreads();
    }
    if (t < nb) bsum[t] = s[t] - v;   // exclusive
}
__global__ void k_scan3(const int* __restrict__ bsum, int* __restrict__ rowptr,
                        int* __restrict__ cursor, int n, int N) {
    int i = blockIdx.x * blockDim.x + threadIdx.x;
    if (i >= n) return;
    int v = rowptr[i] + bsum[i >> 10];
    rowptr[i] = v;
    if (i < N) cursor[i] = v;
}
__global__ void k_fill(const int* __restrict__ aa, const int* __restrict__ ab,
                       const int* __restrict__ ba, int* __restrict__ cursor,
                       int* __restrict__ cse, int E, int Na) {
    int i = blockIdx.x * blockDim.x + threadIdx.x;
    if (i >= 3 * E) return;
    int src, dst, et;
    if (i < E)            { et = 0; src = aa[i]; dst = aa[E + i]; }
    else if (i < 2 * E)   { et = 1; int j = i - E;     src = ab[j]; dst = ab[E + j] + Na; }
    else                  { et = 2; int j = i - 2 * E; src = ba[j]; dst = ba[E + j]; }
    int pos = atomicAdd(&cursor[dst], 1);
    cse[pos] = src | (et << 29);
}

// ---------------------------------------------------------------------------
// Fused HGT edge online-softmax aggregate. One warp per dst node.
// Depth-1 pipeline: cse kept two ahead so k/v prefetch addresses are
// always register-resident.
// ---------------------------------------------------------------------------
__global__ void k_hgt_edges(const float* __restrict__ fa, const float* __restrict__ fb,
                            const int* __restrict__ rowptr, const int* __restrict__ cse,
                            const float* __restrict__ prelL,
                            float* __restrict__ agg, int Na, int N) {
    __shared__ float sp[12];
    if (threadIdx.x < 12) sp[threadIdx.x] = prelL[threadIdx.x];
    __syncthreads();
    int warp = (blockIdx.x * blockDim.x + threadIdx.x) >> 5;
    int lane = threadIdx.x & 31;
    if (warp >= N) return;
    int n = warp;
    const float* qrow = (n < Na) ? (fa + (size_t)n * 640) : (fb + (size_t)(n - Na) * 384);
    float4 q4 = *(const float4*)(qrow + lane * 4);
    int h = lane >> 3;
    int beg = rowptr[n], end = rowptr[n + 1];

    float mx = -INFINITY, sum = 0.f;
    float4 acc = make_float4(0.f, 0.f, 0.f, 0.f);

    int idx = beg;
    int p0 = (idx < end) ? cse[idx] : 0;
    int p1 = (idx + 1 < end) ? cse[idx + 1] : 0;
    float4 k4 = {}, v4 = {};
    if (idx < end) {
        int et = p0 >> 29, src = p0 & 0x1FFFFFFF;
        const float* base = (et < 2) ? (fa + (size_t)src * 640 + 128 + (et << 8))
                                     : (fb + (size_t)src * 384 + 128);
        k4 = *(const float4*)(base + lane * 4);
        v4 = *(const float4*)(base + 128 + lane * 4);
    }
    while (idx < end) {
        // prefetch next k/v from already-resident p1; load p2 in parallel
        int p2 = (idx + 2 < end) ? cse[idx + 2] : 0;
        float4 k4n = {}, v4n = {};
        if (idx + 1 < end) {
            int etn = p1 >> 29, srcn = p1 & 0x1FFFFFFF;
            const float* basen = (etn < 2) ? (fa + (size_t)srcn * 640 + 128 + (etn << 8))
                                           : (fb + (size_t)srcn * 384 + 128);
            k4n = *(const float4*)(basen + lane * 4);
            v4n = *(const float4*)(basen + 128 + lane * 4);
        }
        int et = p0 >> 29;
        float s = q4.x * k4.x + q4.y * k4.y + q4.z * k4.z + q4.w * k4.w;
        s += __shfl_xor_sync(0xffffffffu, s, 1);
        s += __shfl_xor_sync(0xffffffffu, s, 2);
        s += __shfl_xor_sync(0xffffffffu, s, 4);
        float lg = s * sp[et * 4 + h] * 0.17677669529663687f;  // /sqrt(32)
        float mnew = fmaxf(mx, lg);
        float corr = expf(mx - mnew);    // 0 on first edge (mx=-inf)
        float w = expf(lg - mnew);
        sum = sum * corr + w;
        acc.x = acc.x * corr + w * v4.x;
        acc.y = acc.y * corr + w * v4.y;
        acc.z = acc.z * corr + w * v4.z;
        acc.w = acc.w * corr + w * v4.w;
        mx = mnew;
        p0 = p1; p1 = p2; k4 = k4n; v4 = v4n; idx++;
    }
    float inv = 1.f / (sum + 1e-16f);
    acc.x *= inv; acc.y *= inv; acc.z *= inv; acc.w *= inv;
    *(float4*)(agg + (size_t)n * 128 + lane * 4) = acc;
}

// ---------------------------------------------------------------------------
// GAT scorer via CSR (+analytic self loops), online softmax, one pass.
// Depth-1 index pipeline (same mechanism as k_hgt_edges).
// ---------------------------------------------------------------------------
__global__ void k_x1(const float* __restrict__ h, const float* __restrict__ Wg,
                     float* __restrict__ x1, int N) {
    int gw = (blockIdx.x * blockDim.x + threadIdx.x) >> 5;
    int lane = threadIdx.x & 31;
    if (gw >= N) return;
    const float* row = h + (size_t)gw * 128;
    float v = row[lane] * Wg[lane] + row[32 + lane] * Wg[32 + lane]
            + row[64 + lane] * Wg[64 + lane] + row[96 + lane] * Wg[96 + lane];
    v += __shfl_down_sync(0xffffffffu, v, 16);
    v += __shfl_down_sync(0xffffffffu, v, 8);
    v += __shfl_down_sync(0xffffffffu, v, 4);
    v += __shfl_down_sync(0xffffffffu, v, 2);
    v += __shfl_down_sync(0xffffffffu, v, 1);
    if (lane == 0) x1[gw] = v;
}

__global__ void k_gat(const float* __restrict__ x1, const int* __restrict__ rowptr,
                      const int* __restrict__ cse, const float* __restrict__ as_,
                      const float* __restrict__ ad_, const float* __restrict__ bg,
                      float* __restrict__ score, int Na, int N) {
    int n = blockIdx.x * blockDim.x + threadIdx.x;
    if (n >= N) return;
    float a_s = as_[0], a_d = ad_[0];
    float xd = x1[n];
    float eself = xd * (a_s + a_d);
    eself = eself > 0.f ? eself : 0.2f * eself;
    float m = eself, sum = 1.f, num = xd;    // self loop: w=exp(0)=1
    int beg = rowptr[n], end = rowptr[n + 1];

    int i = beg;
    int p0 = (i < end) ? cse[i] : 0;
    float xs = 0.f;
    if (i < end) {
        int src = (p0 & 0x1FFFFFFF) + (((p0 >> 29) == 2) ? Na : 0);
        xs = x1[src];
    }
    while (i < end) {
        int p1 = (i + 1 < end) ? cse[i + 1] : 0;
        float xsn = 0.f;
        if (i + 1 < end) {
            int srcn = (p1 & 0x1FFFFFFF) + (((p1 >> 29) == 2) ? Na : 0);
            xsn = x1[srcn];
        }
        float e = xs * a_s + xd * a_d;
        e = e > 0.f ? e : 0.2f * e;
        float mnew = fmaxf(m, e);
        float corr = expf(m - mnew);
        float w = expf(e - mnew);
        sum = sum * corr + w;
        num = num * corr + w * xs;
        m = mnew;
        p0 = p1; xs = xsn; i++;
    }
    score[n] = num / (sum + 1e-16f) + bg[0];
}

// ---------------------------------------------------------------------------
// Top-K prepass: each block emits its local top-8 (val desc, idx asc)
// ---------------------------------------------------------------------------
__global__ void k_topk(const float* __restrict__ score, float* __restrict__ cval,
                       int* __restrict__ cidx, int N) {
    const float NEG_INF = __int_as_float(0xff800000);
    __shared__ float sval[256];
    __shared__ int   sida[256];
    __shared__ float sred[256];
    __shared__ int   sidr[256];
    int t = threadIdx.x;
    int i = blockIdx.x * 256 + t;
    sval[t] = (i < N) ? score[i] : NEG_INF;
    sida[t] = (i < N) ? i : 0x7fffffff;
    __syncthreads();
    for (int k = 0; k < 8; k++) {
        sred[t] = sval[t]; sidr[t] = sida[t];
        __syncthreads();
        for (int s = 128; s > 0; s >>= 1) {
            if (t < s) {
                if (sred[t + s] > sred[t] ||
                    (sred[t + s] == sred[t] && sidr[t + s] < sidr[t])) {
                    sred[t] = sred[t + s]; sidr[t] = sidr[t + s];
                }
            }
            __syncthreads();
        }
        int win = sidr[0];
        if (t == 0) {
            cval[blockIdx.x * 8 + k] = sred[0];
            cidx[blockIdx.x * 8 + k] = win;
        }
        if (sida[t] == win) sval[t] = NEG_INF;
        __syncthreads();
    }
}

// ---------------------------------------------------------------------------
// Final: global top-8 from candidates, gated readout, 3-layer MLP, nan_to_num.
// ---------------------------------------------------------------------------
__global__ void k_final(const float* __restrict__ h,
                        const float* __restrict__ cval, const int* __restrict__ cidx,
                        int ncand,
                        const float* __restrict__ W1, const float* __restrict__ b1,
                        const float* __restrict__ W2, const float* __restrict__ b2,
                        const float* __restrict__ W3, const float* __restrict__ b3,
                        float* __restrict__ out) {
    const float NEG_INF = __int_as_float(0xff800000);
    __shared__ float cv[MAXCAND];
    __shared__ int   ci[MAXCAND];
    __shared__ float sred[256];
    __shared__ int   sidx[256];
    __shared__ float hp[1024];
    __shared__ int   perm[8];
    __shared__ float vals[8];
    __shared__ float v1[128];
    __shared__ float v2[64];
    int t = threadIdx.x;

    for (int i = t; i < MAXCAND; i += 256) {
        cv[i] = (i < ncand) ? cval[i] : NEG_INF;
        ci[i] = (i < ncand) ? cidx[i] : 0x7fffffff;
    }
    __syncthreads();

    for (int k = 0; k < 8; k++) {
        float bv = NEG_INF; int bi = 0x7fffffff;
        for (int i = t; i < MAXCAND; i += 256) {
            float v = cv[i];
            if (v > bv || (v == bv && ci[i] < bi)) { bv = v; bi = ci[i]; }
        }
        sred[t] = bv; sidx[t] = bi;
        __syncthreads();
        for (int s = 128; s > 0; s >>= 1) {
            if (t < s) {
                if (sred[t + s] > sred[t] ||
                    (sred[t + s] == sred[t] && sidx[t + s] < sidx[t])) {
                    sred[t] = sred[t + s]; sidx[t] = sidx[t + s];
                }
            }
            __syncthreads();
        }
        int win = sidx[0];
        if (t == 0) { perm[k] = win; vals[k] = sred[0]; }
        for (int i = t; i < MAXCAND; i += 256)
            if (ci[i] == win) cv[i] = NEG_INF;
        __syncthreads();
    }

    for (int i = t; i < 1024; i += 256) {
        int k = i >> 7, j = i & 127;
        hp[i] = h[(size_t)perm[k] * 128 + j] * tanhf(vals[k]);
    }
    __syncthreads();

    if (t < 128) {
        float acc = b1[t];
        for (int i = 0; i < 1024; i++) acc += hp[i] * W1[i * 128 + t];
        v1[t] = gelu_f(acc);
    }
    __syncthreads();
    if (t < 64) {
        float acc = b2[t];
        for (int i = 0; i < 128; i++) acc += v1[i] * W2[i * 64 + t];
        v2[t] = gelu_f(acc);
    }
    __syncthreads();
    if (t < 16) {
        float acc = b3[t];
        for (int i = 0; i < 64; i++) acc += v2[i] * W3[i * 16 + t];
        float r = gelu_f(acc);
        if (isnan(r)) r = 0.f;
        else if (isinf(r)) r = (r > 0.f) ? 3.4028234663852886e38f : -3.4028234663852886e38f;
        out[t] = r;
    }
}

// ---------------------------------------------------------------------------
static inline int cdiv(int a, int b) { return (a + b - 1) / b; }

extern "C" void kernel_launch(void* const* d_in, const int* in_sizes, int n_in,
                              void* d_out, int out_size) {
    const float* x_a   = (const float*)d_in[0];
    const float* x_b   = (const float*)d_in[1];
    const int*   ei_aa = (const int*)d_in[2];
    const int*   ei_ab = (const int*)d_in[3];
    const int*   ei_ba = (const int*)d_in[4];
    const float* Wkqv  = (const float*)d_in[5];
    const float* bkqv  = (const float*)d_in[6];
    const float* Wout  = (const float*)d_in[7];
    const float* bout  = (const float*)d_in[8];
    const float* skip  = (const float*)d_in[9];
    const float* arel  = (const float*)d_in[10];
    const float* mrel  = (const float*)d_in[11];
    const float* prel  = (const float*)d_in[12];
    const float* ln_g  = (const float*)d_in[13];
    const float* ln_b  = (const float*)d_in[14];
    const float* Wgat  = (const float*)d_in[15];
    const float* att_s = (const float*)d_in[16];
    const float* att_d = (const float*)d_in[17];
    const float* bgat  = (const float*)d_in[18];
    const float* W1    = (const float*)d_in[19];
    const float* b1    = (const float*)d_in[20];
    const float* W2    = (const float*)d_in[21];
    const float* b2    = (const float*)d_in[22];
    const float* W3    = (const float*)d_in[23];
    const float* b3    = (const float*)d_in[24];

    int Na = in_sizes[0] / 128;
    int Nb = in_sizes[1] / 128;
    int N  = Na + Nb;
    int E  = in_sizes[2] / 2;

    float *hbuf, *fa, *fb, *bcat, *aggb, *x1b, *scoreb, *cvalb;
    __nv_bfloat16 *wAb, *wOb;
    int *degb, *rowptrb, *cursorb, *cseb, *bsumb, *cidxb;
    cudaGetSymbolAddress((void**)&hbuf, g_h);
    cudaGetSymbolAddress((void**)&fa, g_feat_a);
    cudaGetSymbolAddress((void**)&fb, g_feat_b);
    cudaGetSymbolAddress((void**)&bcat, g_bcat);
    cudaGetSymbolAddress((void**)&wAb, g_wA);
    cudaGetSymbolAddress((void**)&wOb, g_wO);
    cudaGetSymbolAddress((void**)&aggb, g_agg);
    cudaGetSymbolAddress((void**)&degb, g_deg);
    cudaGetSymbolAddress((void**)&rowptrb, g_rowptr);
    cudaGetSymbolAddress((void**)&cursorb, g_cursor);
    cudaGetSymbolAddress((void**)&cseb, g_cse);
    cudaGetSymbolAddress((void**)&bsumb, g_bsum);
    cudaGetSymbolAddress((void**)&x1b, g_x1);
    cudaGetSymbolAddress((void**)&scoreb, g_score);
    cudaGetSymbolAddress((void**)&cvalb, g_cval);
    cudaGetSymbolAddress((void**)&cidxb, g_cidx);

    cudaFuncSetAttribute(k_gemm_feat,   cudaFuncAttributeMaxDynamicSharedMemorySize, SMEM_GEMM);
    cudaFuncSetAttribute(k_gemm_out<1>, cudaFuncAttributeMaxDynamicSharedMemorySize, SMEM_GEMM);
    cudaFuncSetAttribute(k_gemm_out<2>, cudaFuncAttributeMaxDynamicSharedMemorySize, SMEM_GEMM);

    // CSR build + weight fold/prep (reused across layers)
    int n1 = N + 1;
    int nbk = cdiv(n1, 1024);
    k_zero_deg<<<cdiv(n1, 256), 256>>>(degb, n1);
    k_count<<<cdiv(3 * E, 256), 256>>>(ei_aa, ei_ab, ei_ba, degb, E, Na);
    k_scan1<<<nbk, 1024>>>(degb, rowptrb, bsumb, n1);
    k_scan2<<<1, 64>>>(bsumb, nbk);
    k_scan3<<<cdiv(n1, 256), 256>>>(bsumb, rowptrb, cursorb, n1, N);
    k_fill<<<cdiv(3 * E, 256), 256>>>(ei_aa, ei_ab, ei_ba, cursorb, cseb, E, Na);
    k_fold2<<<cdiv(30 * 16384 + 3 * 1024, 256), 256>>>(Wkqv, bkqv, Wout, arel, mrel,
                                                       wAb, wOb, bcat);

    int mbA = cdiv(Na, 128), mbB = cdiv(Nb, 128);
    int mbMax = mbA > mbB ? mbA : mbB;

    for (int L = 0; L < 3; L++) {
        const float* Aa = (L == 0) ? x_a : hbuf;
        const float* Ab = (L == 0) ? x_b : hbuf + (size_t)Na * 128;
        k_gemm_feat<<<dim3(8, mbMax), 256, SMEM_GEMM>>>(
            Aa, Ab, Na, Nb, wAb + (size_t)L * 8 * 32768, bcat + L * 1024, fa, fb);
        k_hgt_edges<<<cdiv(N * 32, 256), 256>>>(fa, fb, rowptrb, cseb,
            prel + L * 12, aggb, Na, N);
        if (L == 0) {
            k_gemm_out<2><<<dim3(1, mbA + mbB), 256, SMEM_GEMM>>>(
                aggb, Na, Nb, mbA, wOb + (size_t)L * 2 * 32768, bout + L * 2 * 128,
                hbuf, x_a, x_b, skip + L * 2, ln_g, ln_b);
        } else {
            k_gemm_out<1><<<dim3(1, mbA + mbB), 256, SMEM_GEMM>>>(
                aggb, Na, Nb, mbA, wOb + (size_t)L * 2 * 32768, bout + L * 2 * 128,
                hbuf, hbuf, hbuf + (size_t)Na * 128, skip + L * 2, ln_g, ln_b);
        }
    }

    // GAT scorer + SAGPool + MLP
    k_x1<<<cdiv(N * 32, 256), 256>>>(hbuf, Wgat, x1b, N);
    k_gat<<<cdiv(N, 256), 256>>>(x1b, rowptrb, cseb, att_s, att_d, bgat, scoreb, Na, N);
    int nblk = cdiv(N, 256);
    k_topk<<<nblk, 256>>>(scoreb, cvalb, cidxb, N);
    k_final<<<1, 256>>>(hbuf, cvalb, cidxb, nblk * 8,
                        W1, b1, W2, b2, W3, b3, (float*)d_out);
}